// round 11
// baseline (speedup 1.0000x reference)
#include <cuda_runtime.h>
#include <cuda_fp16.h>
#include <math.h>
#include <stdint.h>

typedef __half fp16;

#define Dc   1024
#define Ec   8
#define Fc   4096
#define NTOK 8192
#define NSLOT (NTOK * 2)
#define PADR 128
#define MAX_TILES 136
#define BM 128
#define BN 128
#define BK 32

// smem stage: 2 tiles (A, B), 128 rows x 80B (32 fp16 = 64B data + 16B pad)
#define ROWB 80
#define ST_A 0
#define ST_B (128 * ROWB)
#define STAGE (2 * 128 * ROWB)      // 20480 B
#define NSTG 4
#define SMEM_DYN (NSTG * STAGE)     // 81920 B

// ---------------- scratch (device globals) ---------------------------------
__device__ __align__(1024) fp16  g_xg [(size_t)NTOK * Dc];            // token-order fp16 x
__device__ __align__(1024) fp16  g_h  [(size_t)(NSLOT + PADR) * Fc];  // slot-order hidden
__device__ __align__(1024) float g_y  [(size_t)NSLOT * Dc];           // slot-order GEMM2 out
__device__ __align__(1024) fp16  g_W1t[(size_t)Ec * Fc * Dc];         // [e][f][d]
__device__ __align__(1024) fp16  g_W2t[(size_t)Ec * Dc * Fc];         // [e][d][f]
__device__ int   g_perm[NSLOT];
__device__ int   g_tok_slot[NTOK * 2];
__device__ int   g_tok_e[NTOK * 2];
__device__ float g_tok_w[NTOK * 2];
__device__ int   g_tile_base[MAX_TILES];
__device__ int   g_tile_expert[MAX_TILES];
__device__ int   g_tile_rows[MAX_TILES];
__device__ int   g_ntiles;

// ---------------- helpers ----------------------------------------------------
__device__ __forceinline__ uint32_t smem_u32(const void* p) {
    uint32_t a;
    asm("{ .reg .u64 t; cvta.to.shared.u64 t, %1; cvt.u32.u64 %0, t; }" : "=r"(a) : "l"(p));
    return a;
}
__device__ __forceinline__ void cp16(uint32_t s, const void* g) {
    asm volatile("cp.async.cg.shared.global [%0], [%1], 16;" :: "r"(s), "l"(g));
}
__device__ __forceinline__ void cp_commit() { asm volatile("cp.async.commit_group;" ::: "memory"); }
#define CP_WAIT(n) asm volatile("cp.async.wait_group %0;" :: "n"(n) : "memory")

__device__ __forceinline__ void ldmx4(uint32_t addr, uint32_t r[4]) {
    asm volatile("ldmatrix.sync.aligned.m8n8.x4.shared.b16 {%0,%1,%2,%3}, [%4];"
        : "=r"(r[0]), "=r"(r[1]), "=r"(r[2]), "=r"(r[3]) : "r"(addr));
}
__device__ __forceinline__ void mma16816(float c[4], const uint32_t a[4], const uint32_t* b) {
    asm volatile("mma.sync.aligned.m16n8k16.row.col.f32.f16.f16.f32 "
        "{%0,%1,%2,%3}, {%4,%5,%6,%7}, {%8,%9}, {%0,%1,%2,%3};"
        : "+f"(c[0]), "+f"(c[1]), "+f"(c[2]), "+f"(c[3])
        : "r"(a[0]), "r"(a[1]), "r"(a[2]), "r"(a[3]), "r"(b[0]), "r"(b[1]));
}
__device__ __forceinline__ float gelu_exact(float v) {
    return 0.5f * v * (1.0f + erff(v * 0.70710678118654752f));
}
__device__ __forceinline__ uint32_t pack2(fp16 a, fp16 b) {
    return (uint32_t)__half_as_ushort(a) | ((uint32_t)__half_as_ushort(b) << 16);
}

// ---------------- gate (fp32 routing + fused x -> fp16 conversion) -----------
__global__ void k_gate(const float* __restrict__ x, const float* __restrict__ Wg,
                       const float* __restrict__ bg) {
    int gtid = blockIdx.x * blockDim.x + threadIdx.x;
    int tok = gtid >> 5, lane = gtid & 31;
    if (tok >= NTOK) return;
    const float* xr = x + (size_t)tok * Dc;
    float acc[Ec];
#pragma unroll
    for (int e = 0; e < Ec; e++) acc[e] = 0.0f;
    for (int d = lane; d < Dc; d += 32) {
        float xv = xr[d];
        const float4* wr = (const float4*)(Wg + (size_t)d * Ec);
        float4 w0 = wr[0], w1 = wr[1];
        acc[0] += xv * w0.x; acc[1] += xv * w0.y; acc[2] += xv * w0.z; acc[3] += xv * w0.w;
        acc[4] += xv * w1.x; acc[5] += xv * w1.y; acc[6] += xv * w1.z; acc[7] += xv * w1.w;
    }
#pragma unroll
    for (int e = 0; e < Ec; e++)
#pragma unroll
        for (int off = 16; off > 0; off >>= 1)
            acc[e] += __shfl_down_sync(0xFFFFFFFFu, acc[e], off);
    if (lane == 0) {
        float v[Ec];
#pragma unroll
        for (int e = 0; e < Ec; e++) v[e] = acc[e] + bg[e];
        int b0 = 0;
#pragma unroll
        for (int e = 1; e < Ec; e++) if (v[e] > v[b0]) b0 = e;
        int b1 = -1; float s = -1e30f;
#pragma unroll
        for (int e = 0; e < Ec; e++) { if (e == b0) continue; if (v[e] > s) { s = v[e]; b1 = e; } }
        float ed = expf(s - v[b0]);
        float p0 = 1.0f / (1.0f + ed);
        float p1 = ed * p0;
        g_tok_e[tok * 2 + 0] = b0; g_tok_e[tok * 2 + 1] = b1;
        g_tok_w[tok * 2 + 0] = p0; g_tok_w[tok * 2 + 1] = p1;
    }
    // fused conversion: x row -> fp16 (token order), reads are L1/L2 hot
    fp16* orow = g_xg + (size_t)tok * Dc;
    for (int d = lane * 2; d < Dc; d += 64) {
        float2 v = *(const float2*)(xr + d);
        *(uint32_t*)(orow + d) = pack2(__float2half_rn(v.x), __float2half_rn(v.y));
    }
}

// ---------------- scatter: single block builds counts, tiles, perm -----------
__global__ void k_scatter() {
    __shared__ int cnt[Ec], cur[Ec];
    int tid = threadIdx.x;
    if (tid < Ec) cnt[tid] = 0;
    __syncthreads();
    for (int t = tid; t < NTOK; t += 1024) {
        atomicAdd(&cnt[g_tok_e[2 * t]], 1);
        atomicAdd(&cnt[g_tok_e[2 * t + 1]], 1);
    }
    __syncthreads();
    if (tid == 0) {
        int o = 0, nt = 0;
        for (int e = 0; e < Ec; e++) {
            int c = cnt[e];
            cur[e] = o;
            for (int s = 0; s < c; s += BM) {
                g_tile_base[nt] = o + s; g_tile_expert[nt] = e;
                g_tile_rows[nt] = min(BM, c - s); nt++;
            }
            o += c;
        }
        g_ntiles = nt;
    }
    __syncthreads();
    for (int t = tid; t < NTOK; t += 1024) {
#pragma unroll
        for (int k = 0; k < 2; k++) {
            int e = g_tok_e[2 * t + k];
            int pos = atomicAdd(&cur[e], 1);
            g_perm[pos] = t;
            g_tok_slot[2 * t + k] = pos;
        }
    }
}

// ---------------- weight transpose: in [e][R][C] fp32 -> out [e][C][R] fp16 --
__global__ void k_tsplit(const float* __restrict__ in, int which, int R, int C) {
    fp16* o = which ? g_W2t : g_W1t;
    __shared__ float t[32][33];
    int e = blockIdx.z;
    int r0 = blockIdx.y * 32, c0 = blockIdx.x * 32;
    int tx = threadIdx.x, ty = threadIdx.y;
    const float* base = in + (size_t)e * R * C;
#pragma unroll
    for (int i = 0; i < 4; i++)
        t[ty + 8 * i][tx] = base[(size_t)(r0 + ty + 8 * i) * C + c0 + tx];
    __syncthreads();
    size_t ob = (size_t)e * C * R;
#pragma unroll
    for (int i = 0; i < 4; i++) {
        float v = t[tx][ty + 8 * i];
        o[ob + (size_t)(c0 + ty + 8 * i) * R + r0 + tx] = __float2half_rn(v);
    }
}

// ---------------- GEMM core (R7 arithmetic; hoisted row pointers) -------------
// CTA 128x128x32, 8 warps in 4(M) x 2(N) grid, warp tile 32x64. 2 CTAs/SM.
// Each thread owns ONE A row and ONE B row (row = tid>>1), two 16B segments.
__device__ __forceinline__ void gemm_core(uint32_t sm0,
        const fp16* __restrict__ aRow, const fp16* __restrict__ bRow,
        int NC, int tid, float (&acc)[2][8][4]) {
    const int lane = tid & 31, wid = tid >> 5;
    const int wm = (wid & 3) * 32, wn = (wid >> 2) * 64;

    const uint32_t a_off = (uint32_t)(wm + (lane & 15)) * ROWB + ((lane & 16) ? 16u : 0u);
    const uint32_t b_off = (uint32_t)(wn + (lane & 7) + ((lane & 16) >> 1)) * ROWB
                           + ((lane & 8) ? 16u : 0u);

    const uint32_t sOff = (uint32_t)(tid >> 1) * ROWB + (uint32_t)(tid & 1) * 32;
    const int cSel = (tid & 1) * 16;   // element offset within row

#pragma unroll
    for (int mt = 0; mt < 2; mt++)
#pragma unroll
        for (int nt = 0; nt < 8; nt++)
#pragma unroll
            for (int q = 0; q < 4; q++) acc[mt][nt][q] = 0.0f;

    // prologue: 3 stages in flight
#pragma unroll
    for (int s = 0; s < 3; s++) {
        uint32_t sb = sm0 + (uint32_t)s * STAGE;
        int k0 = s * BK + cSel;
        cp16(sb + ST_A + sOff,      aRow + k0);
        cp16(sb + ST_A + sOff + 16, aRow + k0 + 8);
        cp16(sb + ST_B + sOff,      bRow + k0);
        cp16(sb + ST_B + sOff + 16, bRow + k0 + 8);
        cp_commit();
    }

    for (int k = 0; k < NC; k++) {
        int rem = NC - 1 - k;
        if (rem >= 2)      { CP_WAIT(2); }
        else if (rem == 1) { CP_WAIT(1); }
        else               { CP_WAIT(0); }
        __syncthreads();
        if (k + 3 < NC) {
            uint32_t sb = sm0 + (uint32_t)((k + 3) & (NSTG - 1)) * STAGE;
            int k0 = (k + 3) * BK + cSel;
            cp16(sb + ST_A + sOff,      aRow + k0);
            cp16(sb + ST_A + sOff + 16, aRow + k0 + 8);
            cp16(sb + ST_B + sOff,      bRow + k0);
            cp16(sb + ST_B + sOff + 16, bRow + k0 + 8);
            cp_commit();
        }
        uint32_t sb = sm0 + (uint32_t)(k & (NSTG - 1)) * STAGE;
#pragma unroll
        for (int kk = 0; kk < 2; kk++) {
            const uint32_t kb = kk * 32;
            uint32_t ah[2][4], bh[4][4];
#pragma unroll
            for (int mt = 0; mt < 2; mt++)
                ldmx4(sb + ST_A + a_off + mt * 16 * ROWB + kb, ah[mt]);
#pragma unroll
            for (int p = 0; p < 4; p++)
                ldmx4(sb + ST_B + b_off + p * 16 * ROWB + kb, bh[p]);
#pragma unroll
            for (int p = 0; p < 4; p++)
#pragma unroll
                for (int q = 0; q < 2; q++)
#pragma unroll
                    for (int mt = 0; mt < 2; mt++)
                        mma16816(acc[mt][p * 2 + q], ah[mt], &bh[p][q * 2]);
        }
        __syncthreads();
    }
}

// ---------------- GEMM1: h[slot] = fp16(gelu(x[perm] @ W1t^T + b1)) ----------
__global__ void __launch_bounds__(256, 2)
k_mma1(const float* __restrict__ b1) {
    int t = blockIdx.y;
    if (t >= g_ntiles) return;
    const int n0 = blockIdx.x * BN;
    const int base = g_tile_base[t], e = g_tile_expert[t], rows = g_tile_rows[t];

    extern __shared__ char dsm[];
    uint32_t sm0 = smem_u32(dsm);
    int tid = threadIdx.x;

    // per-thread source rows: A gathered via perm (clamped for padding rows)
    int arow = tid >> 1;
    int pidx = min(base + arow, NSLOT - 1);
    const fp16* aRow = g_xg + (size_t)g_perm[pidx] * Dc;
    const fp16* bRow = g_W1t + ((size_t)e * Fc + n0 + arow) * Dc;

    float acc[2][8][4];
    gemm_core(sm0, aRow, bRow, Dc / BK, tid, acc);

    const int lane = tid & 31, wid = tid >> 5;
    const int wm = (wid & 3) * 32, wn = (wid >> 2) * 64;
    const int rb = wm + (lane >> 2);
    const int cb = wn + (lane & 3) * 2;
    const float* b1e = b1 + (size_t)e * Fc + n0;
    float bv[8][2];
#pragma unroll
    for (int nt = 0; nt < 8; nt++) {
        bv[nt][0] = b1e[cb + nt * 8];
        bv[nt][1] = b1e[cb + nt * 8 + 1];
    }
#pragma unroll
    for (int mt = 0; mt < 2; mt++)
#pragma unroll
        for (int half = 0; half < 2; half++) {
            int r = rb + mt * 16 + half * 8;
            if (r >= rows) continue;
            size_t ro = (size_t)(base + r) * Fc + n0;
#pragma unroll
            for (int nt = 0; nt < 8; nt++) {
                float v0 = gelu_exact(acc[mt][nt][half * 2 + 0] + bv[nt][0]);
                float v1 = gelu_exact(acc[mt][nt][half * 2 + 1] + bv[nt][1]);
                *(uint32_t*)(g_h + ro + cb + nt * 8) =
                    pack2(__float2half_rn(v0), __float2half_rn(v1));
            }
        }
}

// ---------------- GEMM2: y[slot] = h @ W2t^T + b2 (plain stores) --------------
__global__ void __launch_bounds__(256, 2)
k_mma2(const float* __restrict__ b2) {
    int t = blockIdx.y;
    if (t >= g_ntiles) return;
    const int n0 = blockIdx.x * BN;
    const int base = g_tile_base[t], e = g_tile_expert[t], rows = g_tile_rows[t];

    extern __shared__ char dsm[];
    uint32_t sm0 = smem_u32(dsm);
    int tid = threadIdx.x;

    int arow = tid >> 1;
    const fp16* aRow = g_h + (size_t)(base + arow) * Fc;   // padded rows exist (zero)
    const fp16* bRow = g_W2t + ((size_t)e * Dc + n0 + arow) * Fc;

    float acc[2][8][4];
    gemm_core(sm0, aRow, bRow, Fc / BK, tid, acc);

    const int lane = tid & 31, wid = tid >> 5;
    const int wm = (wid & 3) * 32, wn = (wid >> 2) * 64;
    const int rb = wm + (lane >> 2);
    const int cb = wn + (lane & 3) * 2;
    const float* b2e = b2 + (size_t)e * Dc + n0;
    float bv[8][2];
#pragma unroll
    for (int nt = 0; nt < 8; nt++) {
        bv[nt][0] = b2e[cb + nt * 8];
        bv[nt][1] = b2e[cb + nt * 8 + 1];
    }
#pragma unroll
    for (int mt = 0; mt < 2; mt++)
#pragma unroll
        for (int half = 0; half < 2; half++) {
            int r = rb + mt * 16 + half * 8;
            if (r >= rows) continue;
            float* yrow = g_y + (size_t)(base + r) * Dc + n0;
#pragma unroll
            for (int nt = 0; nt < 8; nt++) {
                int c = cb + nt * 8;
                float2 v;
                v.x = acc[mt][nt][half * 2 + 0] + bv[nt][0];
                v.y = acc[mt][nt][half * 2 + 1] + bv[nt][1];
                *(float2*)(yrow + c) = v;
            }
        }
}

// ---------------- combine: out[t] = w0*y[s0] + w1*y[s1] -----------------------
__global__ void k_combine(float* __restrict__ out) {
    int t = blockIdx.x;
    int tid = threadIdx.x;
    int s0 = g_tok_slot[t * 2 + 0], s1 = g_tok_slot[t * 2 + 1];
    float w0 = g_tok_w[t * 2 + 0],  w1 = g_tok_w[t * 2 + 1];
    const float4* y0 = (const float4*)(g_y + (size_t)s0 * Dc);
    const float4* y1 = (const float4*)(g_y + (size_t)s1 * Dc);
    float4* o = (float4*)(out + (size_t)t * Dc);
    float4 a = y0[tid], b = y1[tid];
    float4 r;
    r.x = w0 * a.x + w1 * b.x;
    r.y = w0 * a.y + w1 * b.y;
    r.z = w0 * a.z + w1 * b.z;
    r.w = w0 * a.w + w1 * b.w;
    o[tid] = r;
}

// ---------------- launch (stream fork-join; mma1 = 4th submitted launch) ------
extern "C" void kernel_launch(void* const* d_in, const int* in_sizes, int n_in,
                              void* d_out, int out_size) {
    const float* x  = (const float*)d_in[0];
    const float* Wg = (const float*)d_in[1];
    const float* bg = (const float*)d_in[2];
    const float* W1 = (const float*)d_in[3];
    const float* b1 = (const float*)d_in[4];
    const float* W2 = (const float*)d_in[5];
    const float* b2 = (const float*)d_in[6];
    float* out = (float*)d_out;

    static cudaStream_t s1 = nullptr, s2 = nullptr;
    static cudaEvent_t e_root = nullptr, e_w1 = nullptr, e_w2 = nullptr;
    static int configured = 0;
    if (!configured) {
        cudaFuncSetAttribute(k_mma1, cudaFuncAttributeMaxDynamicSharedMemorySize, SMEM_DYN);
        cudaFuncSetAttribute(k_mma2, cudaFuncAttributeMaxDynamicSharedMemorySize, SMEM_DYN);
        cudaStreamCreateWithFlags(&s1, cudaStreamNonBlocking);
        cudaStreamCreateWithFlags(&s2, cudaStreamNonBlocking);
        cudaEventCreateWithFlags(&e_root, cudaEventDisableTiming);
        cudaEventCreateWithFlags(&e_w1, cudaEventDisableTiming);
        cudaEventCreateWithFlags(&e_w2, cudaEventDisableTiming);
        configured = 1;
    }

    cudaEventRecord(e_root, 0);
    cudaStreamWaitEvent(s1, e_root, 0);
    cudaStreamWaitEvent(s2, e_root, 0);

    k_gate<<<NTOK / 8, 256>>>(x, Wg, bg);                                     // 0
    k_scatter<<<1, 1024>>>();                                                 // 1
    k_tsplit<<<dim3(Fc / 32, Dc / 32, Ec), dim3(32, 8), 0, s1>>>(W1, 0, Dc, Fc); // 2
    cudaEventRecord(e_w1, s1);
    cudaStreamWaitEvent(0, e_w1, 0);
    k_mma1<<<dim3(Fc / BN, MAX_TILES), 256, SMEM_DYN>>>(b1);                  // 3 -> global 5 (ncu)
    k_tsplit<<<dim3(Dc / 32, Fc / 32, Ec), dim3(32, 8), 0, s2>>>(W2, 1, Fc, Dc); // 4
    cudaEventRecord(e_w2, s2);
    cudaStreamWaitEvent(0, e_w2, 0);
    k_mma2<<<dim3(Dc / BN, MAX_TILES), 256, SMEM_DYN>>>(b2);                  // 5
    k_combine<<<NTOK, 256>>>(out);                                            // 6
}